// round 1
// baseline (speedup 1.0000x reference)
#include <cuda_runtime.h>

#define N 4096

// Physics constants
#define PED_SPEED  1.34f
#define K_GAIN     2.0f
#define ALPHA      10.66f
#define PED_RADIUS 0.3f
#define PED_MASS   60.0f
#define BETTA      0.71f
#define DT         0.4f
#define COST_A     1.0f
#define COST_B     1.0f
#define COST_E     1.0f
#define EPS        1e-8f

#define WARPS_PER_BLOCK 8
#define THREADS (WARPS_PER_BLOCK * 32)

// Kernel 1: pairwise repulsion + attraction + pose propagation.
// One warp per agent i; lanes stride over j; positions staged in shared (SoA).
__global__ __launch_bounds__(THREADS)
void sim_kernel(const float4* __restrict__ state,
                const float2* __restrict__ goals,
                float4* __restrict__ out)
{
    __shared__ float px[N];
    __shared__ float py[N];

    const int tid = threadIdx.x;

    // Cooperative stage of all positions into shared (SoA, conflict-free)
    #pragma unroll
    for (int j = tid; j < N; j += THREADS) {
        float4 s = state[j];
        px[j] = s.x;
        py[j] = s.y;
    }
    __syncthreads();

    const int warp = tid >> 5;
    const int lane = tid & 31;
    const int i = blockIdx.x * WARPS_PER_BLOCK + warp;

    const float xi = px[i];
    const float yi = py[i];

    // exp((2R - d)/B) = exp2( (2R - d) * invB * log2e )
    const float invB_l2e = (1.0f / BETTA) * 1.4426950408889634f;
    const float cA = -invB_l2e;                      // coeff on d
    const float cB = (2.0f * PED_RADIUS) * invB_l2e; // constant term

    float fx = 0.0f;
    float fy = 0.0f;

    #pragma unroll 8
    for (int k = 0; k < N / 32; ++k) {
        const int j = lane + k * 32;
        const float dx = xi - px[j];
        const float dy = yi - py[j];
        const float d2 = fmaf(dx, dx, fmaf(dy, dy, EPS));
        const float rs = rsqrtf(d2);          // 1/d   (MUFU.RSQ)
        const float d  = d2 * rs;             // d
        const float e  = exp2f(fmaf(d, cA, cB)); // MUFU.EX2
        const float coef = (ALPHA * e) * rs;  // mag / dist
        // i==j: dx=dy=0 exactly -> zero contribution, matches eye-mask
        fx = fmaf(coef, dx, fx);
        fy = fmaf(coef, dy, fy);
    }

    // Warp reduction
    #pragma unroll
    for (int off = 16; off > 0; off >>= 1) {
        fx += __shfl_xor_sync(0xffffffffu, fx, off);
        fy += __shfl_xor_sync(0xffffffffu, fy, off);
    }

    if (lane == 0) {
        const float4 s = state[i];
        const float2 g = goals[i];

        // Attraction force
        const float tgx = g.x - s.x;
        const float tgy = g.y - s.y;
        const float gd2 = fmaf(tgx, tgx, fmaf(tgy, tgy, EPS));
        const float inv_gd = rsqrtf(gd2);
        const float afx = K_GAIN * PED_MASS * (PED_SPEED * tgx * inv_gd - s.z);
        const float afy = K_GAIN * PED_MASS * (PED_SPEED * tgy * inv_gd - s.w);

        const float Fx = fx + afx;
        const float Fy = fy + afy;

        // Pose propagation
        float vnx = fmaf(Fx, DT / PED_MASS, s.z);
        float vny = fmaf(Fy, DT / PED_MASS, s.w);
        const float v2 = fmaf(vnx, vnx, fmaf(vny, vny, EPS));
        const float speed = sqrtf(v2);
        const float sc = fminf(1.0f, PED_SPEED / speed);
        vnx *= sc;
        vny *= sc;
        const float pnx = fmaf(vnx, DT, s.x);
        const float pny = fmaf(vny, DT, s.y);

        out[i] = make_float4(pnx, pny, vnx, vny);
    }
}

// Kernel 2: cost. Needs the NEW robot pose out[0] -> separate launch (stream
// order gives the dependency inside the captured graph).
__global__ void cost_kernel(const float4* __restrict__ out_state,
                            const float*  __restrict__ cost_in,
                            const float2* __restrict__ goals,
                            const float*  __restrict__ robot_init_pose,
                            const float4* __restrict__ observed,
                            float* __restrict__ cost_out)
{
    const int i = blockIdx.x * blockDim.x + threadIdx.x;
    if (i >= N) return;

    const float4 r0 = out_state[0];       // new robot pose (broadcast, L2/L1 hot)
    const float ripx = robot_init_pose[0];
    const float ripy = robot_init_pose[1];
    const float2 g0 = goals[0];

    const float gvx = g0.x - ripx;
    const float gvy = g0.y - ripy;
    const float gnorm = sqrtf(gvx * gvx + gvy * gvy) + EPS;
    const float pg = ((r0.x - ripx) * gvx + (r0.y - ripy) * gvy) / gnorm;

    const float4 s = out_state[i];
    const float dx = s.x - r0.x;
    const float dy = s.y - r0.y;
    const float dist = sqrtf(fmaf(dx, dx, fmaf(dy, dy, EPS)));
    const float blame = COST_B * expf(-dist / COST_E);

    const float4 obs = observed[i];
    const float ox = s.x - obs.x;
    const float oy = s.y - obs.y;
    const float dev = fmaf(ox, ox, oy * oy);

    cost_out[i] = cost_in[i] + (-COST_A * pg + blame + dev);
}

extern "C" void kernel_launch(void* const* d_in, const int* in_sizes, int n_in,
                              void* d_out, int out_size)
{
    // metadata order: state (N,4), cost (N,1), goals (N,2),
    //                 robot_init_pose (2,), observed_state (N,4)
    const float4* state    = (const float4*)d_in[0];
    const float*  cost_in  = (const float*) d_in[1];
    const float2* goals    = (const float2*)d_in[2];
    const float*  rip      = (const float*) d_in[3];
    const float4* observed = (const float4*)d_in[4];

    float4* out_state = (float4*)d_out;                 // first N*4 floats
    float*  cost_out  = (float*)d_out + (size_t)N * 4;  // next N floats

    sim_kernel<<<N / WARPS_PER_BLOCK, THREADS>>>(state, goals, out_state);
    cost_kernel<<<N / 256, 256>>>(out_state, cost_in, goals, rip, observed, cost_out);
}

// round 2
// speedup vs baseline: 1.3352x; 1.3352x over previous
#include <cuda_runtime.h>

#define N 4096

#define PED_SPEED  1.34f
#define K_GAIN     2.0f
#define ALPHA      10.66f
#define PED_RADIUS 0.3f
#define PED_MASS   60.0f
#define BETTA      0.71f
#define DT         0.4f
#define COST_A     1.0f
#define COST_B     1.0f
#define COST_E     1.0f
#define EPS        1e-8f

#define WARPS_PER_BLOCK 8
#define THREADS (WARPS_PER_BLOCK * 32)
#define NBLOCKS (N / WARPS_PER_BLOCK)

#define LOG2E 1.4426950408889634f
// log2(ALPHA) = log2(10.66)
#define LOG2_ALPHA 3.4140815f

__device__ __forceinline__ float fast_rsqrt(float x) {
    float y;
    asm("rsqrt.approx.ftz.f32 %0, %1;" : "=f"(y) : "f"(x));
    return y;
}
__device__ __forceinline__ float fast_ex2(float x) {
    float y;
    asm("ex2.approx.ftz.f32 %0, %1;" : "=f"(y) : "f"(x));
    return y;
}

// Fully fused kernel: pairwise repulsion + attraction + propagation + cost.
// One warp per agent i; lanes stride over j reading positions via LDG (L1-hot,
// state is 64KB << 228KB L1). Every block redundantly computes agent 0's force
// so the new robot pose (needed by the cost term) is available in-block.
__global__ __launch_bounds__(THREADS)
void fused_kernel(const float4* __restrict__ state,
                  const float*  __restrict__ cost_in,
                  const float2* __restrict__ goals,
                  const float*  __restrict__ robot_init_pose,
                  const float4* __restrict__ observed,
                  float4* __restrict__ out,
                  float*  __restrict__ cost_out)
{
    __shared__ float redx[WARPS_PER_BLOCK];
    __shared__ float redy[WARPS_PER_BLOCK];

    const int tid  = threadIdx.x;
    const int warp = tid >> 5;
    const int lane = tid & 31;
    const int i    = blockIdx.x * WARPS_PER_BLOCK + warp;

    // positions live at even float2 indices of the float4 state
    const float2* __restrict__ pos2 = (const float2*)state;

    // exp((2R - d)/B) * ALPHA = exp2(d*cA + cB2)
    const float cA  = -(1.0f / BETTA) * LOG2E;
    const float cB2 = (2.0f * PED_RADIUS / BETTA) * LOG2E + LOG2_ALPHA;

    // ---- Phase 1: this block's share of agent-0 (robot) repulsion ----
    const float2 p0 = pos2[0];
    float rfx = 0.0f, rfy = 0.0f;
    #pragma unroll 4
    for (int j = tid; j < N; j += THREADS) {
        const float2 p = pos2[2 * j];
        const float dx = p0.x - p.x;
        const float dy = p0.y - p.y;
        const float d2 = fmaf(dx, dx, fmaf(dy, dy, EPS));
        const float rs = fast_rsqrt(d2);
        const float d  = d2 * rs;
        const float e  = fast_ex2(fmaf(d, cA, cB2)); // ALPHA * exp(...)
        const float coef = e * rs;
        rfx = fmaf(coef, dx, rfx);
        rfy = fmaf(coef, dy, rfy);
    }
    #pragma unroll
    for (int off = 16; off > 0; off >>= 1) {
        rfx += __shfl_xor_sync(0xffffffffu, rfx, off);
        rfy += __shfl_xor_sync(0xffffffffu, rfy, off);
    }
    if (lane == 0) { redx[warp] = rfx; redy[warp] = rfy; }

    // ---- Phase 2: repulsion on this warp's agent i ----
    const float2 pi = pos2[2 * i];
    const float xi = pi.x;
    const float yi = pi.y;

    float fx = 0.0f, fy = 0.0f;
    #pragma unroll 8
    for (int k = 0; k < N / 32; ++k) {
        const float2 p = pos2[2 * (lane + k * 32)];
        const float dx = xi - p.x;
        const float dy = yi - p.y;
        const float d2 = fmaf(dx, dx, fmaf(dy, dy, EPS));
        const float rs = fast_rsqrt(d2);
        const float d  = d2 * rs;
        const float e  = fast_ex2(fmaf(d, cA, cB2));
        const float coef = e * rs;
        // i==j contributes exactly zero (dx=dy=0), matching the eye mask
        fx = fmaf(coef, dx, fx);
        fy = fmaf(coef, dy, fy);
    }
    #pragma unroll
    for (int off = 16; off > 0; off >>= 1) {
        fx += __shfl_xor_sync(0xffffffffu, fx, off);
        fy += __shfl_xor_sync(0xffffffffu, fy, off);
    }

    __syncthreads();  // redx/redy visible

    if (lane == 0) {
        // ---- robot total repulsion (block-local, deterministic) ----
        float Rfx = 0.0f, Rfy = 0.0f;
        #pragma unroll
        for (int w = 0; w < WARPS_PER_BLOCK; ++w) { Rfx += redx[w]; Rfy += redy[w]; }

        // ---- robot new pose (agent 0) ----
        const float4 s0 = state[0];
        const float2 g0 = goals[0];
        float r0x, r0y;
        {
            const float tgx = g0.x - s0.x;
            const float tgy = g0.y - s0.y;
            const float inv_gd = fast_rsqrt(fmaf(tgx, tgx, fmaf(tgy, tgy, EPS)));
            const float Fx = Rfx + K_GAIN * PED_MASS * (PED_SPEED * tgx * inv_gd - s0.z);
            const float Fy = Rfy + K_GAIN * PED_MASS * (PED_SPEED * tgy * inv_gd - s0.w);
            float vnx = fmaf(Fx, DT / PED_MASS, s0.z);
            float vny = fmaf(Fy, DT / PED_MASS, s0.w);
            const float spd = sqrtf(fmaf(vnx, vnx, fmaf(vny, vny, EPS)));
            const float sc = fminf(1.0f, PED_SPEED / spd);
            vnx *= sc; vny *= sc;
            r0x = fmaf(vnx, DT, s0.x);
            r0y = fmaf(vny, DT, s0.y);
        }

        // ---- agent i: attraction + propagation ----
        const float4 s = state[i];
        const float2 g = goals[i];
        const float tgx = g.x - s.x;
        const float tgy = g.y - s.y;
        const float inv_gd = fast_rsqrt(fmaf(tgx, tgx, fmaf(tgy, tgy, EPS)));
        const float Fx = fx + K_GAIN * PED_MASS * (PED_SPEED * tgx * inv_gd - s.z);
        const float Fy = fy + K_GAIN * PED_MASS * (PED_SPEED * tgy * inv_gd - s.w);

        float vnx = fmaf(Fx, DT / PED_MASS, s.z);
        float vny = fmaf(Fy, DT / PED_MASS, s.w);
        const float spd = sqrtf(fmaf(vnx, vnx, fmaf(vny, vny, EPS)));
        const float sc = fminf(1.0f, PED_SPEED / spd);
        vnx *= sc; vny *= sc;
        const float pnx = fmaf(vnx, DT, s.x);
        const float pny = fmaf(vny, DT, s.y);

        out[i] = make_float4(pnx, pny, vnx, vny);

        // ---- cost for agent i ----
        const float ripx = robot_init_pose[0];
        const float ripy = robot_init_pose[1];
        const float gvx = g0.x - ripx;
        const float gvy = g0.y - ripy;
        const float gnorm = sqrtf(gvx * gvx + gvy * gvy) + EPS;
        const float pg = ((r0x - ripx) * gvx + (r0y - ripy) * gvy) / gnorm;

        const float ddx = pnx - r0x;
        const float ddy = pny - r0y;
        const float dist = sqrtf(fmaf(ddx, ddx, fmaf(ddy, ddy, EPS)));
        const float blame = COST_B * fast_ex2(-dist * (LOG2E / COST_E));

        const float4 obs = observed[i];
        const float ox = pnx - obs.x;
        const float oy = pny - obs.y;
        const float dev = fmaf(ox, ox, oy * oy);

        cost_out[i] = cost_in[i] + (-COST_A * pg + blame + dev);
    }
}

extern "C" void kernel_launch(void* const* d_in, const int* in_sizes, int n_in,
                              void* d_out, int out_size)
{
    const float4* state    = (const float4*)d_in[0];
    const float*  cost_in  = (const float*) d_in[1];
    const float2* goals    = (const float2*)d_in[2];
    const float*  rip      = (const float*) d_in[3];
    const float4* observed = (const float4*)d_in[4];

    float4* out_state = (float4*)d_out;
    float*  cost_out  = (float*)d_out + (size_t)N * 4;

    fused_kernel<<<NBLOCKS, THREADS>>>(state, cost_in, goals, rip, observed,
                                       out_state, cost_out);
}

// round 3
// speedup vs baseline: 1.3868x; 1.0387x over previous
#include <cuda_runtime.h>

#define N 4096

#define PED_SPEED  1.34f
#define K_GAIN     2.0f
#define ALPHA      10.66f
#define PED_RADIUS 0.3f
#define PED_MASS   60.0f
#define BETTA      0.71f
#define DT         0.4f
#define COST_A     1.0f
#define COST_B     1.0f
#define COST_E     1.0f
#define EPS        1e-8f

#define LOG2E      1.4426950408889634f
#define LOG2_ALPHA 3.4140815f

#define THREADS 512
#define WPB     16            // warps per block
#define APB     8             // agents per block (2 warps per agent, j split in half)
#define NBLK    (N / APB)     // 512 blocks -> one wave at 4 blocks/SM
#define JHALF   (N / 2)       // 2048 j's per warp
#define JITERS  (JHALF / 32)  // 64 inner iterations

typedef unsigned long long u64;

__device__ __forceinline__ float fast_rsqrt(float x) {
    float y; asm("rsqrt.approx.ftz.f32 %0, %1;" : "=f"(y) : "f"(x)); return y;
}
__device__ __forceinline__ float fast_ex2(float x) {
    float y; asm("ex2.approx.ftz.f32 %0, %1;" : "=f"(y) : "f"(x)); return y;
}
__device__ __forceinline__ u64 f2_add(u64 a, u64 b) {
    u64 o; asm("add.rn.f32x2 %0, %1, %2;" : "=l"(o) : "l"(a), "l"(b)); return o;
}
__device__ __forceinline__ u64 f2_fma(u64 a, u64 b, u64 c) {
    u64 o; asm("fma.rn.f32x2 %0, %1, %2, %3;" : "=l"(o) : "l"(a), "l"(b), "l"(c)); return o;
}
__device__ __forceinline__ u64 pack2(float x, float y) {
    u64 o; asm("mov.b64 %0, {%1, %2};" : "=l"(o) : "f"(x), "f"(y)); return o;
}
__device__ __forceinline__ void unpack2(u64 v, float& x, float& y) {
    asm("mov.b64 {%0, %1}, %2;" : "=f"(x), "=f"(y) : "l"(v));
}

// One pair: facc += (ALPHA*exp((2R-d)/B)/d) * (pi - pj), with npj = -pj.
__device__ __forceinline__ void pair_acc(u64 pixy, u64 npj, u64& facc,
                                         float cA, float cB2)
{
    const u64 dxy = f2_add(pixy, npj);          // (dx, dy) packed
    float dx, dy; unpack2(dxy, dx, dy);          // register-pair alias (free)
    const float d2 = fmaf(dx, dx, fmaf(dy, dy, EPS));
    const float rs = fast_rsqrt(d2);             // 1/d
    const float d  = d2 * rs;                    // d
    const float e  = fast_ex2(fmaf(d, cA, cB2)); // ALPHA * exp((2R-d)/B)
    const float coef = e * rs;
    facc = f2_fma(pack2(coef, coef), dxy, facc); // i==j: dxy==0 -> no contribution
}

__global__ __launch_bounds__(THREADS, 4)
void fused_kernel(const float4* __restrict__ state,
                  const float*  __restrict__ cost_in,
                  const float2* __restrict__ goals,
                  const float*  __restrict__ robot_init_pose,
                  const float4* __restrict__ observed,
                  float4* __restrict__ out,
                  float*  __restrict__ cost_out)
{
    __shared__ u64    spos[N];       // packed (-x, -y) per agent, 32 KB
    __shared__ float2 fpart[WPB];    // per-warp partial forces
    __shared__ float2 rpart[WPB];    // per-warp robot partials

    const int tid  = threadIdx.x;
    const int warp = tid >> 5;
    const int lane = tid & 31;

    // ---- Stage negated positions into shared ----
    #pragma unroll
    for (int k = 0; k < N / THREADS; ++k) {
        const int j = tid + k * THREADS;
        const float4 s = state[j];
        spos[j] = pack2(-s.x, -s.y);
    }
    __syncthreads();

    const float cA  = -(1.0f / BETTA) * LOG2E;
    const float cB2 = (2.0f * PED_RADIUS / BETTA) * LOG2E + LOG2_ALPHA;

    // ---- Phase 1: block-redundant robot (agent 0) repulsion ----
    float p0x, p0y; unpack2(spos[0], p0x, p0y);
    const u64 p0xy = pack2(-p0x, -p0y);          // back to +pos (exact)
    u64 racc = 0;                                 // (0.0f, 0.0f)
    #pragma unroll
    for (int k = 0; k < N / THREADS; ++k)
        pair_acc(p0xy, spos[tid + k * THREADS], racc, cA, cB2);

    float rfx, rfy; unpack2(racc, rfx, rfy);
    #pragma unroll
    for (int off = 16; off > 0; off >>= 1) {
        rfx += __shfl_xor_sync(0xffffffffu, rfx, off);
        rfy += __shfl_xor_sync(0xffffffffu, rfy, off);
    }
    if (lane == 0) rpart[warp] = make_float2(rfx, rfy);

    // ---- Phase 2: this warp's (agent, j-half) repulsion ----
    const int aslot = warp >> 1;                  // 0..7
    const int half  = warp & 1;                   // 0..1
    const int i     = blockIdx.x * APB + aslot;

    float nix, niy; unpack2(spos[i], nix, niy);
    const u64 pixy = pack2(-nix, -niy);

    u64 facc = 0;
    const int jbase = half * JHALF + lane;
    #pragma unroll 4
    for (int k = 0; k < JITERS; ++k)
        pair_acc(pixy, spos[jbase + k * 32], facc, cA, cB2);

    float fx, fy; unpack2(facc, fx, fy);
    #pragma unroll
    for (int off = 16; off > 0; off >>= 1) {
        fx += __shfl_xor_sync(0xffffffffu, fx, off);
        fy += __shfl_xor_sync(0xffffffffu, fy, off);
    }
    if (lane == 0) fpart[warp] = make_float2(fx, fy);

    __syncthreads();

    // ---- Epilogue: one thread per agent (tid 0..7) ----
    if (tid < APB) {
        const int ia = blockIdx.x * APB + tid;

        // robot total repulsion (deterministic in-block order)
        float Rfx = 0.0f, Rfy = 0.0f;
        #pragma unroll
        for (int w = 0; w < WPB; ++w) { Rfx += rpart[w].x; Rfy += rpart[w].y; }

        // robot new pose
        const float4 s0 = state[0];
        const float2 g0 = goals[0];
        float r0x, r0y;
        {
            const float tgx = g0.x - s0.x;
            const float tgy = g0.y - s0.y;
            const float inv_gd = fast_rsqrt(fmaf(tgx, tgx, fmaf(tgy, tgy, EPS)));
            const float Fx = Rfx + K_GAIN * PED_MASS * (PED_SPEED * tgx * inv_gd - s0.z);
            const float Fy = Rfy + K_GAIN * PED_MASS * (PED_SPEED * tgy * inv_gd - s0.w);
            float vnx = fmaf(Fx, DT / PED_MASS, s0.z);
            float vny = fmaf(Fy, DT / PED_MASS, s0.w);
            const float spd = sqrtf(fmaf(vnx, vnx, fmaf(vny, vny, EPS)));
            const float sc = fminf(1.0f, PED_SPEED / spd);
            vnx *= sc; vny *= sc;
            r0x = fmaf(vnx, DT, s0.x);
            r0y = fmaf(vny, DT, s0.y);
        }

        // this agent: combine halves, attraction + propagation
        const float afx = fpart[2 * tid].x + fpart[2 * tid + 1].x;
        const float afy = fpart[2 * tid].y + fpart[2 * tid + 1].y;

        const float4 s = state[ia];
        const float2 g = goals[ia];
        const float tgx = g.x - s.x;
        const float tgy = g.y - s.y;
        const float inv_gd = fast_rsqrt(fmaf(tgx, tgx, fmaf(tgy, tgy, EPS)));
        const float Fx = afx + K_GAIN * PED_MASS * (PED_SPEED * tgx * inv_gd - s.z);
        const float Fy = afy + K_GAIN * PED_MASS * (PED_SPEED * tgy * inv_gd - s.w);

        float vnx = fmaf(Fx, DT / PED_MASS, s.z);
        float vny = fmaf(Fy, DT / PED_MASS, s.w);
        const float spd = sqrtf(fmaf(vnx, vnx, fmaf(vny, vny, EPS)));
        const float sc = fminf(1.0f, PED_SPEED / spd);
        vnx *= sc; vny *= sc;
        const float pnx = fmaf(vnx, DT, s.x);
        const float pny = fmaf(vny, DT, s.y);

        out[ia] = make_float4(pnx, pny, vnx, vny);

        // cost
        const float ripx = robot_init_pose[0];
        const float ripy = robot_init_pose[1];
        const float gvx = g0.x - ripx;
        const float gvy = g0.y - ripy;
        const float gnorm = sqrtf(gvx * gvx + gvy * gvy) + EPS;
        const float pg = ((r0x - ripx) * gvx + (r0y - ripy) * gvy) / gnorm;

        const float ddx = pnx - r0x;
        const float ddy = pny - r0y;
        const float dist = sqrtf(fmaf(ddx, ddx, fmaf(ddy, ddy, EPS)));
        const float blame = COST_B * fast_ex2(-dist * (LOG2E / COST_E));

        const float4 obs = observed[ia];
        const float ox = pnx - obs.x;
        const float oy = pny - obs.y;
        const float dev = fmaf(ox, ox, oy * oy);

        cost_out[ia] = cost_in[ia] + (-COST_A * pg + blame + dev);
    }
}

extern "C" void kernel_launch(void* const* d_in, const int* in_sizes, int n_in,
                              void* d_out, int out_size)
{
    const float4* state    = (const float4*)d_in[0];
    const float*  cost_in  = (const float*) d_in[1];
    const float2* goals    = (const float2*)d_in[2];
    const float*  rip      = (const float*) d_in[3];
    const float4* observed = (const float4*)d_in[4];

    float4* out_state = (float4*)d_out;
    float*  cost_out  = (float*)d_out + (size_t)N * 4;

    fused_kernel<<<NBLK, THREADS>>>(state, cost_in, goals, rip, observed,
                                    out_state, cost_out);
}

// round 4
// speedup vs baseline: 1.5223x; 1.0977x over previous
#include <cuda_runtime.h>

#define N 4096

#define PED_SPEED  1.34f
#define K_GAIN     2.0f
#define ALPHA      10.66f
#define PED_RADIUS 0.3f
#define PED_MASS   60.0f
#define BETTA      0.71f
#define DT         0.4f
#define COST_A     1.0f
#define COST_B     1.0f
#define COST_E     1.0f
#define EPS        1e-8f

#define LOG2E      1.4426950408889634f
#define LOG2_ALPHA 3.4140815f

#define THREADS 896            // 28 warps
#define WPB     28
#define APB     14             // agents per block, 2 warps per agent
#define NBLK    296            // 2 * 148 -> exactly 2 blocks per SM, one wave
#define JHALF   (N / 2)        // 2048 j's per warp
#define J4      (JHALF / 2)    // 1024 float4 (2 agents each) per warp-half
#define J4ITERS (J4 / 32)      // 32 inner iterations, 2 pairs each

__device__ __forceinline__ float fast_rsqrt(float x) {
    float y; asm("rsqrt.approx.ftz.f32 %0, %1;" : "=f"(y) : "f"(x)); return y;
}
__device__ __forceinline__ float fast_ex2(float x) {
    float y; asm("ex2.approx.ftz.f32 %0, %1;" : "=f"(y) : "f"(x)); return y;
}

// One pair: f += (ALPHA*exp((2R-d)/B)/d) * (pi - pj). i==j gives exactly 0.
__device__ __forceinline__ void pair_acc(float xi, float yi, float pjx, float pjy,
                                         float& fx, float& fy, float cA, float cB2)
{
    const float dx = xi - pjx;
    const float dy = yi - pjy;
    const float d2 = fmaf(dx, dx, fmaf(dy, dy, EPS));
    const float rs = fast_rsqrt(d2);             // 1/d
    const float d  = d2 * rs;                    // d
    const float e  = fast_ex2(fmaf(d, cA, cB2)); // ALPHA * exp((2R-d)/B)
    const float coef = e * rs;
    fx = fmaf(coef, dx, fx);
    fy = fmaf(coef, dy, fy);
}

__global__ __launch_bounds__(THREADS, 2)
void fused_kernel(const float4* __restrict__ state,
                  const float*  __restrict__ cost_in,
                  const float2* __restrict__ goals,
                  const float*  __restrict__ robot_init_pose,
                  const float4* __restrict__ observed,
                  float4* __restrict__ out,
                  float*  __restrict__ cost_out)
{
    __shared__ float2 spos[N];       // (x, y) per agent, 32 KB
    __shared__ float2 fpart[WPB];    // per-warp partial forces
    __shared__ float2 rpart[16];     // robot partials (warps 0..15)

    const int tid  = threadIdx.x;
    const int warp = tid >> 5;
    const int lane = tid & 31;

    // ---- Stage positions into shared ----
    for (int j = tid; j < N; j += THREADS) {
        const float4 s = state[j];
        spos[j] = make_float2(s.x, s.y);
    }
    __syncthreads();

    const float cA  = -(1.0f / BETTA) * LOG2E;
    const float cB2 = (2.0f * PED_RADIUS / BETTA) * LOG2E + LOG2_ALPHA;

    const float4* __restrict__ spos4 = (const float4*)spos;  // 2 agents per entry

    // ---- Phase 1: robot (agent 0) repulsion, warps 0..15 only ----
    if (warp < 16) {
        const float2 p0 = spos[0];
        float rfx = 0.0f, rfy = 0.0f;
        #pragma unroll
        for (int k = 0; k < 4; ++k) {                 // 4 * 512 = 2048 float4 = 4096 pairs
            const float4 p = spos4[tid + k * 512];
            pair_acc(p0.x, p0.y, p.x, p.y, rfx, rfy, cA, cB2);
            pair_acc(p0.x, p0.y, p.z, p.w, rfx, rfy, cA, cB2);
        }
        #pragma unroll
        for (int off = 16; off > 0; off >>= 1) {
            rfx += __shfl_xor_sync(0xffffffffu, rfx, off);
            rfy += __shfl_xor_sync(0xffffffffu, rfy, off);
        }
        if (lane == 0) rpart[warp] = make_float2(rfx, rfy);
    }

    // ---- Phase 2: this warp's (agent, j-half) repulsion ----
    const int aslot = warp >> 1;                  // 0..13
    const int half  = warp & 1;                   // 0..1
    const int i     = blockIdx.x * APB + aslot;

    if (i < N) {
        const float2 pi = spos[i];
        const float xi = pi.x, yi = pi.y;

        float fx = 0.0f, fy = 0.0f;
        const int jbase = half * J4 + lane;       // float4 index
        #pragma unroll 4
        for (int k = 0; k < J4ITERS; ++k) {
            const float4 p = spos4[jbase + k * 32];
            pair_acc(xi, yi, p.x, p.y, fx, fy, cA, cB2);
            pair_acc(xi, yi, p.z, p.w, fx, fy, cA, cB2);
        }
        #pragma unroll
        for (int off = 16; off > 0; off >>= 1) {
            fx += __shfl_xor_sync(0xffffffffu, fx, off);
            fy += __shfl_xor_sync(0xffffffffu, fy, off);
        }
        if (lane == 0) fpart[warp] = make_float2(fx, fy);
    }

    __syncthreads();

    // ---- Epilogue: one thread per agent (tid 0..APB-1) ----
    if (tid < APB) {
        const int ia = blockIdx.x * APB + tid;
        if (ia < N) {
            // robot total repulsion (deterministic in-block order)
            float Rfx = 0.0f, Rfy = 0.0f;
            #pragma unroll
            for (int w = 0; w < 16; ++w) { Rfx += rpart[w].x; Rfy += rpart[w].y; }

            // robot new pose
            const float4 s0 = state[0];
            const float2 g0 = goals[0];
            float r0x, r0y;
            {
                const float tgx = g0.x - s0.x;
                const float tgy = g0.y - s0.y;
                const float inv_gd = fast_rsqrt(fmaf(tgx, tgx, fmaf(tgy, tgy, EPS)));
                const float Fx = Rfx + K_GAIN * PED_MASS * (PED_SPEED * tgx * inv_gd - s0.z);
                const float Fy = Rfy + K_GAIN * PED_MASS * (PED_SPEED * tgy * inv_gd - s0.w);
                float vnx = fmaf(Fx, DT / PED_MASS, s0.z);
                float vny = fmaf(Fy, DT / PED_MASS, s0.w);
                const float spd = sqrtf(fmaf(vnx, vnx, fmaf(vny, vny, EPS)));
                const float sc = fminf(1.0f, PED_SPEED / spd);
                vnx *= sc; vny *= sc;
                r0x = fmaf(vnx, DT, s0.x);
                r0y = fmaf(vny, DT, s0.y);
            }

            // this agent: combine halves, attraction + propagation
            const float afx = fpart[2 * tid].x + fpart[2 * tid + 1].x;
            const float afy = fpart[2 * tid].y + fpart[2 * tid + 1].y;

            const float4 s = state[ia];
            const float2 g = goals[ia];
            const float tgx = g.x - s.x;
            const float tgy = g.y - s.y;
            const float inv_gd = fast_rsqrt(fmaf(tgx, tgx, fmaf(tgy, tgy, EPS)));
            const float Fx = afx + K_GAIN * PED_MASS * (PED_SPEED * tgx * inv_gd - s.z);
            const float Fy = afy + K_GAIN * PED_MASS * (PED_SPEED * tgy * inv_gd - s.w);

            float vnx = fmaf(Fx, DT / PED_MASS, s.z);
            float vny = fmaf(Fy, DT / PED_MASS, s.w);
            const float spd = sqrtf(fmaf(vnx, vnx, fmaf(vny, vny, EPS)));
            const float sc = fminf(1.0f, PED_SPEED / spd);
            vnx *= sc; vny *= sc;
            const float pnx = fmaf(vnx, DT, s.x);
            const float pny = fmaf(vny, DT, s.y);

            out[ia] = make_float4(pnx, pny, vnx, vny);

            // cost
            const float ripx = robot_init_pose[0];
            const float ripy = robot_init_pose[1];
            const float gvx = g0.x - ripx;
            const float gvy = g0.y - ripy;
            const float gnorm = sqrtf(gvx * gvx + gvy * gvy) + EPS;
            const float pg = ((r0x - ripx) * gvx + (r0y - ripy) * gvy) / gnorm;

            const float ddx = pnx - r0x;
            const float ddy = pny - r0y;
            const float dist = sqrtf(fmaf(ddx, ddx, fmaf(ddy, ddy, EPS)));
            const float blame = COST_B * fast_ex2(-dist * (LOG2E / COST_E));

            const float4 obs = observed[ia];
            const float ox = pnx - obs.x;
            const float oy = pny - obs.y;
            const float dev = fmaf(ox, ox, oy * oy);

            cost_out[ia] = cost_in[ia] + (-COST_A * pg + blame + dev);
        }
    }
}

extern "C" void kernel_launch(void* const* d_in, const int* in_sizes, int n_in,
                              void* d_out, int out_size)
{
    const float4* state    = (const float4*)d_in[0];
    const float*  cost_in  = (const float*) d_in[1];
    const float2* goals    = (const float2*)d_in[2];
    const float*  rip      = (const float*) d_in[3];
    const float4* observed = (const float4*)d_in[4];

    float4* out_state = (float4*)d_out;
    float*  cost_out  = (float*)d_out + (size_t)N * 4;

    fused_kernel<<<NBLK, THREADS>>>(state, cost_in, goals, rip, observed,
                                    out_state, cost_out);
}

// round 5
// speedup vs baseline: 1.7836x; 1.1716x over previous
#include <cuda_runtime.h>

#define N 4096

#define PED_SPEED  1.34f
#define K_GAIN     2.0f
#define ALPHA      10.66f
#define PED_RADIUS 0.3f
#define PED_MASS   60.0f
#define BETTA      0.71f
#define DT         0.4f
#define COST_A     1.0f
#define COST_B     1.0f
#define COST_E     1.0f
#define EPS        1e-8f

#define LOG2E      1.4426950408889634f
#define LOG2_ALPHA 3.4140815f

#define THREADS 1024
#define WPB     32
#define J4ALL   (N / 2)        // 2048 float4 entries (2 agents each)
#define J4ITERS (J4ALL / 32)   // 64 inner iterations per warp, 2 pairs each

__device__ __forceinline__ float fast_rsqrt(float x) {
    float y; asm("rsqrt.approx.ftz.f32 %0, %1;" : "=f"(y) : "f"(x)); return y;
}
__device__ __forceinline__ float fast_ex2(float x) {
    float y; asm("ex2.approx.ftz.f32 %0, %1;" : "=f"(y) : "f"(x)); return y;
}

// One pair: f += (ALPHA*exp((2R-d)/B)/d) * (pi - pj). i==j gives exactly 0.
__device__ __forceinline__ void pair_acc(float xi, float yi, float pjx, float pjy,
                                         float& fx, float& fy, float cA, float cB2)
{
    const float dx = xi - pjx;
    const float dy = yi - pjy;
    const float d2 = fmaf(dx, dx, fmaf(dy, dy, EPS));
    const float rs = fast_rsqrt(d2);             // 1/d   (MUFU.RSQ)
    const float d  = d2 * rs;                    // d
    const float e  = fast_ex2(fmaf(d, cA, cB2)); // ALPHA * exp((2R-d)/B)  (MUFU.EX2)
    const float coef = e * rs;
    fx = fmaf(coef, dx, fx);
    fy = fmaf(coef, dy, fy);
}

// One fat block per SM, one wave. 1 warp per agent, high register budget
// (launch_bounds 1024,1 -> up to 64 regs) so ptxas can keep many independent
// pair chains in flight and hide the RSQ/EX2 latency.
__global__ __launch_bounds__(THREADS, 1)
void fused_kernel(const float4* __restrict__ state,
                  const float*  __restrict__ cost_in,
                  const float2* __restrict__ goals,
                  const float*  __restrict__ robot_init_pose,
                  const float4* __restrict__ observed,
                  float4* __restrict__ out,
                  float*  __restrict__ cost_out,
                  int apb)                        // agents per block (runtime, ~27)
{
    __shared__ float2 spos[N];       // (x, y) per agent, 32 KB
    __shared__ float2 fpart[WPB];    // per-warp agent forces
    __shared__ float2 rpart[WPB];    // per-warp robot partials

    const int tid  = threadIdx.x;
    const int warp = tid >> 5;
    const int lane = tid & 31;

    // ---- Stage positions into shared (4 iters) ----
    #pragma unroll
    for (int k = 0; k < N / THREADS; ++k) {
        const int j = tid + k * THREADS;
        const float4 s = state[j];
        spos[j] = make_float2(s.x, s.y);
    }
    __syncthreads();

    const float cA  = -(1.0f / BETTA) * LOG2E;
    const float cB2 = (2.0f * PED_RADIUS / BETTA) * LOG2E + LOG2_ALPHA;

    const float4* __restrict__ spos4 = (const float4*)spos;  // 2 agents per entry

    // ---- Phase 1: robot (agent 0) repulsion, all 32 warps (4 pairs/thread) ----
    {
        const float2 p0 = spos[0];
        float rfx = 0.0f, rfy = 0.0f;
        #pragma unroll
        for (int k = 0; k < J4ALL / THREADS; ++k) {   // 2 iterations
            const float4 p = spos4[tid + k * THREADS];
            pair_acc(p0.x, p0.y, p.x, p.y, rfx, rfy, cA, cB2);
            pair_acc(p0.x, p0.y, p.z, p.w, rfx, rfy, cA, cB2);
        }
        #pragma unroll
        for (int off = 16; off > 0; off >>= 1) {
            rfx += __shfl_xor_sync(0xffffffffu, rfx, off);
            rfy += __shfl_xor_sync(0xffffffffu, rfy, off);
        }
        if (lane == 0) rpart[warp] = make_float2(rfx, rfy);
    }

    // ---- Phase 2: one warp per agent, full j sweep (64 iters x 2 pairs) ----
    const int i = blockIdx.x * apb + warp;
    if (warp < apb && i < N) {
        const float2 pi = spos[i];
        const float xi = pi.x, yi = pi.y;

        float fx = 0.0f, fy = 0.0f;
        #pragma unroll 8
        for (int k = 0; k < J4ITERS; ++k) {
            const float4 p = spos4[lane + k * 32];
            pair_acc(xi, yi, p.x, p.y, fx, fy, cA, cB2);
            pair_acc(xi, yi, p.z, p.w, fx, fy, cA, cB2);
        }
        #pragma unroll
        for (int off = 16; off > 0; off >>= 1) {
            fx += __shfl_xor_sync(0xffffffffu, fx, off);
            fy += __shfl_xor_sync(0xffffffffu, fy, off);
        }
        if (lane == 0) fpart[warp] = make_float2(fx, fy);
    }

    __syncthreads();

    // ---- Epilogue: one thread per agent ----
    if (tid < apb) {
        const int ia = blockIdx.x * apb + tid;
        if (ia < N) {
            // robot total repulsion (deterministic in-block order)
            float Rfx = 0.0f, Rfy = 0.0f;
            #pragma unroll
            for (int w = 0; w < WPB; ++w) { Rfx += rpart[w].x; Rfy += rpart[w].y; }

            // robot new pose
            const float4 s0 = state[0];
            const float2 g0 = goals[0];
            float r0x, r0y;
            {
                const float tgx = g0.x - s0.x;
                const float tgy = g0.y - s0.y;
                const float inv_gd = fast_rsqrt(fmaf(tgx, tgx, fmaf(tgy, tgy, EPS)));
                const float Fx = Rfx + K_GAIN * PED_MASS * (PED_SPEED * tgx * inv_gd - s0.z);
                const float Fy = Rfy + K_GAIN * PED_MASS * (PED_SPEED * tgy * inv_gd - s0.w);
                float vnx = fmaf(Fx, DT / PED_MASS, s0.z);
                float vny = fmaf(Fy, DT / PED_MASS, s0.w);
                const float spd = sqrtf(fmaf(vnx, vnx, fmaf(vny, vny, EPS)));
                const float sc = fminf(1.0f, PED_SPEED / spd);
                vnx *= sc; vny *= sc;
                r0x = fmaf(vnx, DT, s0.x);
                r0y = fmaf(vny, DT, s0.y);
            }

            // this agent: attraction + propagation
            const float afx = fpart[tid].x;
            const float afy = fpart[tid].y;

            const float4 s = state[ia];
            const float2 g = goals[ia];
            const float tgx = g.x - s.x;
            const float tgy = g.y - s.y;
            const float inv_gd = fast_rsqrt(fmaf(tgx, tgx, fmaf(tgy, tgy, EPS)));
            const float Fx = afx + K_GAIN * PED_MASS * (PED_SPEED * tgx * inv_gd - s.z);
            const float Fy = afy + K_GAIN * PED_MASS * (PED_SPEED * tgy * inv_gd - s.w);

            float vnx = fmaf(Fx, DT / PED_MASS, s.z);
            float vny = fmaf(Fy, DT / PED_MASS, s.w);
            const float spd = sqrtf(fmaf(vnx, vnx, fmaf(vny, vny, EPS)));
            const float sc = fminf(1.0f, PED_SPEED / spd);
            vnx *= sc; vny *= sc;
            const float pnx = fmaf(vnx, DT, s.x);
            const float pny = fmaf(vny, DT, s.y);

            out[ia] = make_float4(pnx, pny, vnx, vny);

            // cost
            const float ripx = robot_init_pose[0];
            const float ripy = robot_init_pose[1];
            const float gvx = g0.x - ripx;
            const float gvy = g0.y - ripy;
            const float gnorm = sqrtf(gvx * gvx + gvy * gvy) + EPS;
            const float pg = ((r0x - ripx) * gvx + (r0y - ripy) * gvy) / gnorm;

            const float ddx = pnx - r0x;
            const float ddy = pny - r0y;
            const float dist = sqrtf(fmaf(ddx, ddx, fmaf(ddy, ddy, EPS)));
            const float blame = COST_B * fast_ex2(-dist * (LOG2E / COST_E));

            const float4 obs = observed[ia];
            const float ox = pnx - obs.x;
            const float oy = pny - obs.y;
            const float dev = fmaf(ox, ox, oy * oy);

            cost_out[ia] = cost_in[ia] + (-COST_A * pg + blame + dev);
        }
    }
}

extern "C" void kernel_launch(void* const* d_in, const int* in_sizes, int n_in,
                              void* d_out, int out_size)
{
    const float4* state    = (const float4*)d_in[0];
    const float*  cost_in  = (const float*) d_in[1];
    const float2* goals    = (const float2*)d_in[2];
    const float*  rip      = (const float*) d_in[3];
    const float4* observed = (const float4*)d_in[4];

    float4* out_state = (float4*)d_out;
    float*  cost_out  = (float*)d_out + (size_t)N * 4;

    // One block per SM, one wave. Queried at graph-capture time (host code
    // runs only during capture; grid dims are baked into the graph).
    int nsm = 0;
    if (cudaDeviceGetAttribute(&nsm, cudaDevAttrMultiProcessorCount, 0) != cudaSuccess
        || nsm <= 0) nsm = 148;
    if (nsm > N) nsm = N;
    const int apb = (N + nsm - 1) / nsm;   // agents per block (<= 32 warps)

    fused_kernel<<<nsm, THREADS>>>(state, cost_in, goals, rip, observed,
                                   out_state, cost_out, apb);
}